// round 10
// baseline (speedup 1.0000x reference)
#include <cuda_runtime.h>
#include <cstdint>

// SparseLayer: 100000 independent tiny linear MLPs (5 -> 2 -> 2 -> 1), batch 128.
// Linear chain collapses per-net to v = w2 @ w1 @ w0 (1x5); out[b] = v . x[:,b].
//
// HBM-bound (~256 MB stream-once x). x loads: L2::evict_first (keeps L2 free to
// absorb out writebacks + weights -> R4's win). R7: front-batched x loads.
// R8: persistent grid-stride — exactly one wave of CTAs (148 SMs x 8 blocks),
// each warp loops over ~11 nets; no wave transitions, setup paid once.

#define N_NETS    100000
#define INTERFACE 5
#define BATCH     128
#define NUM_SMS   148
#define BLOCKS    (NUM_SMS * 8)
#define WARPS_TOTAL (BLOCKS * 8)

__global__ __launch_bounds__(256) void sparse_layer_kernel(
    const float* __restrict__ x,    // [N_NETS*5, 128]
    const float* __restrict__ w0,   // [N_NETS, 2, 5]
    const float* __restrict__ w1,   // [N_NETS, 2, 2]
    const float* __restrict__ w2,   // [N_NETS, 1, 2]
    float* __restrict__ out)        // [N_NETS, 128]
{
    const int warp0 = (blockIdx.x * blockDim.x + threadIdx.x) >> 5;
    const int lane  = threadIdx.x & 31;

    uint64_t pol_first;
    asm("createpolicy.fractional.L2::evict_first.b64 %0, 1.0;" : "=l"(pol_first));

    for (int net = warp0; net < N_NETS; net += WARPS_TOTAL) {
        // ---- Front-batch the 5 bandwidth-carrying x loads (evict_first) ----
        const float* xbase = x + (size_t)net * INTERFACE * BATCH + lane * 4;
        float r[INTERFACE][4];
#pragma unroll
        for (int i = 0; i < INTERFACE; ++i) {
            const float* p = xbase + i * BATCH;
            asm volatile(
                "ld.global.nc.L2::cache_hint.v4.f32 {%0,%1,%2,%3}, [%4], %5;"
                : "=f"(r[i][0]), "=f"(r[i][1]), "=f"(r[i][2]), "=f"(r[i][3])
                : "l"(p), "l"(pol_first));
        }

        // ---- Weight loads scheduled into the x-load latency shadow ----
        const float4 w1v = __ldg(reinterpret_cast<const float4*>(w1) + net);
        const float2 w2v = __ldg(reinterpret_cast<const float2*>(w2) + net);
        const float2* W0p = reinterpret_cast<const float2*>(w0 + (size_t)net * 10);
        float2 w0v[5];
#pragma unroll
        for (int i = 0; i < 5; ++i) w0v[i] = __ldg(W0p + i);
        const float* W0 = &w0v[0].x;   // 10 contiguous floats in registers

        // u = w2 @ w1 (1x2)
        const float a0 = fmaf(w2v.y, w1v.z, w2v.x * w1v.x);
        const float a1 = fmaf(w2v.y, w1v.w, w2v.x * w1v.y);

        // v = u @ w0 (1x5)
        float v[INTERFACE];
#pragma unroll
        for (int i = 0; i < INTERFACE; ++i)
            v[i] = fmaf(a1, W0[INTERFACE + i], a0 * W0[i]);

        // ---- Accumulate ----
        float acc0 = 0.f, acc1 = 0.f, acc2 = 0.f, acc3 = 0.f;
#pragma unroll
        for (int i = 0; i < INTERFACE; ++i) {
            acc0 = fmaf(v[i], r[i][0], acc0);
            acc1 = fmaf(v[i], r[i][1], acc1);
            acc2 = fmaf(v[i], r[i][2], acc2);
            acc3 = fmaf(v[i], r[i][3], acc3);
        }

        reinterpret_cast<float4*>(out)[(size_t)net * (BATCH / 4) + lane] =
            make_float4(acc0, acc1, acc2, acc3);
    }
}

extern "C" void kernel_launch(void* const* d_in, const int* in_sizes, int n_in,
                              void* d_out, int out_size)
{
    const float* x  = (const float*)d_in[0];
    const float* w0 = (const float*)d_in[1];
    const float* w1 = (const float*)d_in[2];
    const float* w2 = (const float*)d_in[3];
    float* out = (float*)d_out;

    sparse_layer_kernel<<<BLOCKS, 256>>>(x, w0, w1, w2, out);
}

// round 14
// speedup vs baseline: 1.0614x; 1.0614x over previous
#include <cuda_runtime.h>
#include <cstdint>

// SparseLayer: 100000 independent tiny linear MLPs (5 -> 2 -> 2 -> 1), batch 128.
// Linear chain collapses per-net to v = w2 @ w1 @ w0 (1x5); out[b] = v . x[:,b].
//
// Best-known structure (R7): one warp per net, flat launch (contiguous nets ->
// sequential DRAM pages), five front-batched 16B x loads with L2::evict_first
// (keeps L2 free to absorb out writebacks + weights), weight loads scheduled
// into the x-load latency shadow. R10 adds L2::256B fetch-granularity hint on
// the sequential x stream.

#define N_NETS    100000
#define INTERFACE 5
#define BATCH     128

__global__ __launch_bounds__(256) void sparse_layer_kernel(
    const float* __restrict__ x,    // [N_NETS*5, 128]
    const float* __restrict__ w0,   // [N_NETS, 2, 5]
    const float* __restrict__ w1,   // [N_NETS, 2, 2]
    const float* __restrict__ w2,   // [N_NETS, 1, 2]
    float* __restrict__ out)        // [N_NETS, 128]
{
    const int warp = (blockIdx.x * blockDim.x + threadIdx.x) >> 5;
    const int lane = threadIdx.x & 31;
    if (warp >= N_NETS) return;

    uint64_t pol_first;
    asm("createpolicy.fractional.L2::evict_first.b64 %0, 1.0;" : "=l"(pol_first));

    // ---- Front-batch the 5 bandwidth-carrying x loads ----
    // evict_first policy + 256B L2 fetch granularity on the sequential stream.
    const float* xbase = x + (size_t)warp * INTERFACE * BATCH + lane * 4;
    float r[INTERFACE][4];
#pragma unroll
    for (int i = 0; i < INTERFACE; ++i) {
        const float* p = xbase + i * BATCH;
        asm volatile(
            "ld.global.nc.L2::cache_hint.L2::256B.v4.f32 {%0,%1,%2,%3}, [%4], %5;"
            : "=f"(r[i][0]), "=f"(r[i][1]), "=f"(r[i][2]), "=f"(r[i][3])
            : "l"(p), "l"(pol_first));
    }

    // ---- Weight loads: vectorized __ldg, scheduled into the x-load shadow ----
    const float4 w1v = __ldg(reinterpret_cast<const float4*>(w1) + warp);
    const float2 w2v = __ldg(reinterpret_cast<const float2*>(w2) + warp);
    const float2* W0p = reinterpret_cast<const float2*>(w0 + (size_t)warp * 10);
    float2 w0v[5];
#pragma unroll
    for (int i = 0; i < 5; ++i) w0v[i] = __ldg(W0p + i);
    const float* W0 = &w0v[0].x;   // 10 contiguous floats in registers

    // u = w2 @ w1 (1x2)
    const float a0 = fmaf(w2v.y, w1v.z, w2v.x * w1v.x);
    const float a1 = fmaf(w2v.y, w1v.w, w2v.x * w1v.y);

    // v = u @ w0 (1x5)
    float v[INTERFACE];
#pragma unroll
    for (int i = 0; i < INTERFACE; ++i)
        v[i] = fmaf(a1, W0[INTERFACE + i], a0 * W0[i]);

    // ---- Accumulate ----
    float acc0 = 0.f, acc1 = 0.f, acc2 = 0.f, acc3 = 0.f;
#pragma unroll
    for (int i = 0; i < INTERFACE; ++i) {
        acc0 = fmaf(v[i], r[i][0], acc0);
        acc1 = fmaf(v[i], r[i][1], acc1);
        acc2 = fmaf(v[i], r[i][2], acc2);
        acc3 = fmaf(v[i], r[i][3], acc3);
    }

    reinterpret_cast<float4*>(out)[(size_t)warp * (BATCH / 4) + lane] =
        make_float4(acc0, acc1, acc2, acc3);
}

extern "C" void kernel_launch(void* const* d_in, const int* in_sizes, int n_in,
                              void* d_out, int out_size)
{
    const float* x  = (const float*)d_in[0];
    const float* w0 = (const float*)d_in[1];
    const float* w1 = (const float*)d_in[2];
    const float* w2 = (const float*)d_in[3];
    float* out = (float*)d_out;

    const int warps_per_block = 256 / 32;  // 8 nets per block
    const int grid = (N_NETS + warps_per_block - 1) / warps_per_block;
    sparse_layer_kernel<<<grid, 256>>>(x, w0, w1, w2, out);
}